// round 11
// baseline (speedup 1.0000x reference)
#include <cuda_runtime.h>
#include <cuda_bf16.h>
#include <cuda_fp16.h>
#include <cstdint>

#define N_NODES 50000
#define EMBED_DIM 128
#define N_EDGES 500000
#define NBLK ((N_NODES + 255) / 256)   // 196

// ---------------- device scratch (zero-initialized at module load) ----------------
__device__ int   g_cnt[N_NODES];          // self-cleaning histogram
__device__ int   g_bsum[NBLK];
__device__ int   g_rowstart[N_NODES + 1];
__device__ int   g_cursor[N_NODES];
__device__ unsigned long long g_edge[N_EDGES];   // packed {val_f32<<32 | col}
__device__ float g_dis[N_NODES];
__device__ __half g_xh[N_NODES * EMBED_DIM];     // fp16 image of x
__device__ __half g_hh[N_NODES * EMBED_DIM];     // fp16 layer-1 activations
// W split images, transposed: Bh[layer][n*128+k] = bf16_hi(W[k][n])
__device__ __nv_bfloat16 g_Bh[2][128 * 128];
__device__ __nv_bfloat16 g_Bl[2][128 * 128];

// ---------------- hist (+ weight prep + x->fp16 + identity copy) ----------------
__global__ void k_hist(const int* __restrict__ ei,
                       const float* __restrict__ W1, const float* __restrict__ W2,
                       const float* __restrict__ x, float* __restrict__ out2) {
    int e = blockIdx.x * blockDim.x + threadIdx.x;
    if (e < N_EDGES) {
        unsigned d = (unsigned)ei[N_EDGES + e];
        if (d < N_NODES) atomicAdd(&g_cnt[d], 1);
    }
    // side job 1: weight split/transpose (first 128 blocks, 32768 elems)
    if (blockIdx.x < 128) {
        int idx = blockIdx.x * blockDim.x + threadIdx.x;
        int layer = idx >> 14;
        int t = idx & 16383;
        int k = t >> 7, n = t & 127;
        const float* W = layer ? W2 : W1;
        float w = W[k * 128 + n];
        __nv_bfloat16 wh = __float2bfloat16(w);
        __nv_bfloat16 wl = __float2bfloat16(w - __bfloat162float(wh));
        g_Bh[layer][n * 128 + k] = wh;
        g_Bl[layer][n * 128 + k] = wl;
    }
    // side job 2: x -> fp16 image + identity copy (grid-stride float4)
    {
        int nthreads = gridDim.x * blockDim.x;
        int total4 = N_NODES * EMBED_DIM / 4;
        for (int i = blockIdx.x * blockDim.x + threadIdx.x; i < total4; i += nthreads) {
            float4 v = ((const float4*)x)[i];
            __half2* dst = (__half2*)g_xh + i * 2;
            dst[0] = __floats2half2_rn(v.x, v.y);
            dst[1] = __floats2half2_rn(v.z, v.w);
            if (out2) ((float4*)out2)[i] = v;
        }
    }
}

__global__ __launch_bounds__(256) void k_blocksum() {
    __shared__ int sh[256];
    int t = threadIdx.x;
    int i = blockIdx.x * 256 + t;
    sh[t] = (i < N_NODES) ? g_cnt[i] : 0;
    __syncthreads();
    #pragma unroll
    for (int off = 128; off > 0; off >>= 1) {
        if (t < off) sh[t] += sh[t + off];
        __syncthreads();
    }
    if (t == 0) g_bsum[blockIdx.x] = sh[0];
}

__global__ __launch_bounds__(256) void k_scan_final() {
    __shared__ int red[256];
    __shared__ int sh[256];
    int t = threadIdx.x;
    int i = blockIdx.x * 256 + t;
    red[t] = (t < blockIdx.x) ? g_bsum[t] : 0;
    __syncthreads();
    #pragma unroll
    for (int off = 128; off > 0; off >>= 1) {
        if (t < off) red[t] += red[t + off];
        __syncthreads();
    }
    int blockoff = red[0];
    int v = (i < N_NODES) ? g_cnt[i] : 0;
    sh[t] = v;
    __syncthreads();
    #pragma unroll
    for (int off = 1; off < 256; off <<= 1) {
        int add = (t >= off) ? sh[t - off] : 0;
        __syncthreads();
        sh[t] += add;
        __syncthreads();
    }
    if (i < N_NODES) {
        int rs = blockoff + sh[t] - v;
        g_rowstart[i] = rs;
        g_cursor[i]   = rs;
        g_dis[i]      = rsqrtf((float)(v + 1));
        g_cnt[i]      = 0;                 // self-clean for next replay
    }
    if (i == 0) g_rowstart[N_NODES] = N_EDGES;
}

__global__ void k_fill(const int* __restrict__ ei) {
    int e = blockIdx.x * blockDim.x + threadIdx.x;
    if (e >= N_EDGES) return;
    unsigned s = (unsigned)ei[e];
    unsigned d = (unsigned)ei[N_EDGES + e];
    if (s >= N_NODES || d >= N_NODES) return;
    int pos = atomicAdd(&g_cursor[d], 1);
    float nm = g_dis[s] * g_dis[d];
    g_edge[pos] = ((unsigned long long)__float_as_uint(nm) << 32) | (unsigned long long)s;
}

// ---------------- fused gather + HMMA bf16x3 GEMM + bias + tanh ----------------
#define PAD 136
#define A_IMG (64 * PAD * 2)
#define B_IMG (128 * PAD * 2)
#define SM_AH 0
#define SM_AL A_IMG
#define SM_BH (2 * A_IMG)
#define SM_BL (2 * A_IMG + B_IMG)
#define MMA_SMEM (2 * A_IMG + 2 * B_IMG)   // 104448 B

__device__ __forceinline__ uint32_t smem_u32(const void* p) {
    uint32_t a;
    asm("{ .reg .u64 t; cvta.to.shared.u64 t, %1; cvt.u32.u64 %0, t; }" : "=r"(a) : "l"(p));
    return a;
}
__device__ __forceinline__ void ldm_x4(uint32_t* r, uint32_t addr) {
    asm volatile("ldmatrix.sync.aligned.m8n8.x4.shared.b16 {%0,%1,%2,%3}, [%4];"
                 : "=r"(r[0]), "=r"(r[1]), "=r"(r[2]), "=r"(r[3]) : "r"(addr));
}
__device__ __forceinline__ void mma_bf16(float* d, const uint32_t* a, uint32_t b0, uint32_t b1) {
    asm volatile(
        "mma.sync.aligned.m16n8k16.row.col.f32.bf16.bf16.f32 "
        "{%0,%1,%2,%3}, {%4,%5,%6,%7}, {%8,%9}, {%0,%1,%2,%3};"
        : "+f"(d[0]), "+f"(d[1]), "+f"(d[2]), "+f"(d[3])
        : "r"(a[0]), "r"(a[1]), "r"(a[2]), "r"(a[3]), "r"(b0), "r"(b1));
}
__device__ __forceinline__ float4 h4_to_f4(uint2 p, float nm) {
    __half2 lo = *(__half2*)&p.x;
    __half2 hi = *(__half2*)&p.y;
    float2 a = __half22float2(lo);
    float2 b = __half22float2(hi);
    float4 r;
    r.x = nm * a.x; r.y = nm * a.y; r.z = nm * b.x; r.w = nm * b.y;
    return r;
}

__global__ __launch_bounds__(256) void k_fused_gemm(const float* __restrict__ x,
                                                    const float* __restrict__ bvec,
                                                    float* __restrict__ out, int layer) {
    extern __shared__ char sm[];
    __nv_bfloat16* sAH = (__nv_bfloat16*)(sm + SM_AH);
    __nv_bfloat16* sAL = (__nv_bfloat16*)(sm + SM_AL);
    int tid = threadIdx.x, wid = tid >> 5, lane = tid & 31;
    int row0 = blockIdx.x * 64;

    // stage B images
    {
        const uint4* bh = (const uint4*)g_Bh[layer];
        const uint4* bl = (const uint4*)g_Bl[layer];
        #pragma unroll
        for (int i = 0; i < 8; i++) {
            int idx = tid + i * 256;
            int n = idx >> 4, c = idx & 15;
            *(uint4*)(sm + SM_BH + n * (PAD * 2) + c * 16) = bh[idx];
            *(uint4*)(sm + SM_BL + n * (PAD * 2) + c * 16) = bl[idx];
        }
    }

    // fused gather: warp w handles tile rows w*8 .. w*8+7; lane owns cols lane*4..+3
    const __half* in = layer ? g_hh : g_xh;
    #pragma unroll
    for (int p = 0; p < 8; p++) {
        int r = wid * 8 + p;
        int node = row0 + r;
        float4 acc = make_float4(0.f, 0.f, 0.f, 0.f);
        if (node < N_NODES) {
            float di = g_dis[node];
            float c = di * di;
            if (layer == 0) {   // self term from exact fp32 x
                float4 raw = ((const float4*)(x + (size_t)node * EMBED_DIM))[lane];
                acc.x = raw.x * c; acc.y = raw.y * c; acc.z = raw.z * c; acc.w = raw.w * c;
            } else {
                uint2 q = ((const uint2*)(in + (size_t)node * EMBED_DIM))[lane];
                acc = h4_to_f4(q, c);
            }
            int j   = g_rowstart[node];
            int end = g_rowstart[node + 1];
            for (; j + 4 <= end; j += 4) {
                unsigned long long p0 = g_edge[j],     p1 = g_edge[j + 1];
                unsigned long long p2 = g_edge[j + 2], p3 = g_edge[j + 3];
                int s0 = (int)(unsigned)p0, s1 = (int)(unsigned)p1;
                int s2 = (int)(unsigned)p2, s3 = (int)(unsigned)p3;
                float n0 = __uint_as_float((unsigned)(p0 >> 32));
                float n1 = __uint_as_float((unsigned)(p1 >> 32));
                float n2 = __uint_as_float((unsigned)(p2 >> 32));
                float n3 = __uint_as_float((unsigned)(p3 >> 32));
                uint2 q0 = ((const uint2*)(in + (size_t)s0 * EMBED_DIM))[lane];
                uint2 q1 = ((const uint2*)(in + (size_t)s1 * EMBED_DIM))[lane];
                uint2 q2 = ((const uint2*)(in + (size_t)s2 * EMBED_DIM))[lane];
                uint2 q3 = ((const uint2*)(in + (size_t)s3 * EMBED_DIM))[lane];
                float4 v0 = h4_to_f4(q0, n0);
                float4 v1 = h4_to_f4(q1, n1);
                float4 v2 = h4_to_f4(q2, n2);
                float4 v3 = h4_to_f4(q3, n3);
                acc.x += v0.x + v1.x + v2.x + v3.x;
                acc.y += v0.y + v1.y + v2.y + v3.y;
                acc.z += v0.z + v1.z + v2.z + v3.z;
                acc.w += v0.w + v1.w + v2.w + v3.w;
            }
            for (; j < end; j++) {
                unsigned long long p0 = g_edge[j];
                int s0 = (int)(unsigned)p0;
                float n0 = __uint_as_float((unsigned)(p0 >> 32));
                uint2 q0 = ((const uint2*)(in + (size_t)s0 * EMBED_DIM))[lane];
                float4 v0 = h4_to_f4(q0, n0);
                acc.x += v0.x; acc.y += v0.y; acc.z += v0.z; acc.w += v0.w;
            }
        }
        // bf16 hi/lo split directly into smem A tiles
        int cb = lane * 4;
        float av[4] = {acc.x, acc.y, acc.z, acc.w};
        #pragma unroll
        for (int q = 0; q < 4; q++) {
            __nv_bfloat16 ah = __float2bfloat16(av[q]);
            __nv_bfloat16 al = __float2bfloat16(av[q] - __bfloat162float(ah));
            sAH[r * PAD + cb + q] = ah;
            sAL[r * PAD + cb + q] = al;
        }
    }
    __syncthreads();

    int m0 = (wid & 3) * 16;
    int n_base = (wid >> 2) * 64;

    uint32_t sb = smem_u32(sm);
    uint32_t aoff = (uint32_t)((m0 + (lane & 15)) * (PAD * 2) + (lane & 16));
    uint32_t aAddrH = sb + SM_AH + aoff;
    uint32_t aAddrL = sb + SM_AL + aoff;
    uint32_t bAddrH[4], bAddrL[4];
    #pragma unroll
    for (int p = 0; p < 4; p++) {
        int n = n_base + p * 16 + (lane & 7) + ((lane >> 1) & 8);
        uint32_t boff = (uint32_t)(n * (PAD * 2) + (lane & 8) * 2);
        bAddrH[p] = sb + SM_BH + boff;
        bAddrL[p] = sb + SM_BL + boff;
    }

    float d[8][4];
    #pragma unroll
    for (int t = 0; t < 8; t++)
        #pragma unroll
        for (int q = 0; q < 4; q++) d[t][q] = 0.0f;

    #pragma unroll
    for (int kk = 0; kk < 8; kk++) {
        uint32_t kb = kk * 32;
        uint32_t ah[4], al[4], bh[4][4], bl[4][4];
        ldm_x4(ah, aAddrH + kb);
        ldm_x4(al, aAddrL + kb);
        #pragma unroll
        for (int p = 0; p < 4; p++) {
            ldm_x4(bh[p], bAddrH[p] + kb);
            ldm_x4(bl[p], bAddrL[p] + kb);
        }
        #pragma unroll
        for (int p = 0; p < 4; p++) {
            #pragma unroll
            for (int q = 0; q < 2; q++) {
                int t = p * 2 + q;
                mma_bf16(d[t], ah, bh[p][2 * q], bh[p][2 * q + 1]);
                mma_bf16(d[t], ah, bl[p][2 * q], bl[p][2 * q + 1]);
                mma_bf16(d[t], al, bh[p][2 * q], bh[p][2 * q + 1]);
            }
        }
    }

    int g = lane >> 2;
    int c2 = (lane & 3) * 2;
    int rowA = row0 + m0 + g;
    int rowB = rowA + 8;
    #pragma unroll
    for (int t = 0; t < 8; t++) {
        int col = n_base + t * 8 + c2;
        float bx = bvec[col], by = bvec[col + 1];
        float hax = tanhf(d[t][0] + bx), hay = tanhf(d[t][1] + by);
        float hbx = tanhf(d[t][2] + bx), hby = tanhf(d[t][3] + by);
        if (layer == 0) {  // -> fp16 activations
            if (rowA < N_NODES)
                *(__half2*)(g_hh + (size_t)rowA * EMBED_DIM + col) = __floats2half2_rn(hax, hay);
            if (rowB < N_NODES)
                *(__half2*)(g_hh + (size_t)rowB * EMBED_DIM + col) = __floats2half2_rn(hbx, hby);
        } else {           // -> fp32 output
            if (rowA < N_NODES) {
                float2 o; o.x = hax; o.y = hay;
                *(float2*)(out + (size_t)rowA * EMBED_DIM + col) = o;
            }
            if (rowB < N_NODES) {
                float2 o; o.x = hbx; o.y = hby;
                *(float2*)(out + (size_t)rowB * EMBED_DIM + col) = o;
            }
        }
    }
}

extern "C" void kernel_launch(void* const* d_in, const int* in_sizes, int n_in,
                              void* d_out, int out_size) {
    const float* x  = (const float*)d_in[0];
    const int*   ei = (const int*)d_in[1];
    const float* W1 = (const float*)d_in[2];
    const float* b1 = (const float*)d_in[3];
    const float* W2 = (const float*)d_in[4];
    const float* b2 = (const float*)d_in[5];
    float* out = (float*)d_out;

    cudaFuncSetAttribute(k_fused_gemm,
                         cudaFuncAttributeMaxDynamicSharedMemorySize, MMA_SMEM);

    const int NT = 256;
    int blksE = (N_EDGES + NT - 1) / NT;
    int blksG = (N_NODES + 63) / 64;

    float* out2 = (out_size >= 2 * N_NODES * EMBED_DIM)
                ? out + (size_t)N_NODES * EMBED_DIM : nullptr;

    // CSR build + weight prep + x->fp16 + identity copy
    k_hist<<<blksE, NT>>>(ei, W1, W2, x, out2);
    k_blocksum<<<NBLK, NT>>>();
    k_scan_final<<<NBLK, NT>>>();
    k_fill<<<blksE, NT>>>(ei);

    // fused layers
    k_fused_gemm<<<blksG, NT, MMA_SMEM>>>(x, b1, out, 0);
    k_fused_gemm<<<blksG, NT, MMA_SMEM>>>(x, b2, out, 1);
}

// round 12
// speedup vs baseline: 1.2951x; 1.2951x over previous
#include <cuda_runtime.h>
#include <cuda_bf16.h>
#include <cstdint>

#define N_NODES 50000
#define EMBED_DIM 128
#define N_EDGES 500000
#define HALF_E (N_EDGES / 2)
#define NBLK ((N_NODES + 255) / 256)   // 196

// ---------------- device scratch (zero-initialized at module load) ----------------
__device__ int   g_cnt[N_NODES];          // self-cleaning histogram
__device__ int   g_bsum[NBLK];
__device__ int   g_rowstart[N_NODES + 1];
__device__ int   g_cursor[N_NODES];
__device__ unsigned long long g_edge[N_EDGES];   // packed {val_f32<<32 | col}
__device__ float g_dis[N_NODES];
__device__ float g_agg[N_NODES * EMBED_DIM];
__device__ float g_h[N_NODES * EMBED_DIM];
// W split images, transposed: Bh[layer][n*128+k] = bf16_hi(W[k][n])
__device__ __nv_bfloat16 g_Bh[2][128 * 128];
__device__ __nv_bfloat16 g_Bl[2][128 * 128];

// ---------------- hist: 2 edges/thread (+ fused weight prep) ----------------
__global__ void k_hist(const int* __restrict__ ei,
                       const float* __restrict__ W1, const float* __restrict__ W2) {
    int t = blockIdx.x * blockDim.x + threadIdx.x;
    if (t < HALF_E) {
        unsigned d0 = (unsigned)ei[N_EDGES + t];
        unsigned d1 = (unsigned)ei[N_EDGES + HALF_E + t];
        if (d0 < N_NODES) atomicAdd(&g_cnt[d0], 1);
        if (d1 < N_NODES) atomicAdd(&g_cnt[d1], 1);
    }
    // side job: weight split/transpose (first 128 blocks, 32768 elems)
    if (blockIdx.x < 128) {
        int idx = blockIdx.x * blockDim.x + threadIdx.x;
        int layer = idx >> 14;
        int e = idx & 16383;
        int k = e >> 7, n = e & 127;
        const float* W = layer ? W2 : W1;
        float w = W[k * 128 + n];
        __nv_bfloat16 wh = __float2bfloat16(w);
        __nv_bfloat16 wl = __float2bfloat16(w - __bfloat162float(wh));
        g_Bh[layer][n * 128 + k] = wh;
        g_Bl[layer][n * 128 + k] = wl;
    }
}

// ---------------- warp-shuffle block sum ----------------
__global__ __launch_bounds__(256) void k_blocksum() {
    int t = threadIdx.x;
    int i = blockIdx.x * 256 + t;
    int v = (i < N_NODES) ? g_cnt[i] : 0;
    #pragma unroll
    for (int off = 16; off > 0; off >>= 1) v += __shfl_down_sync(0xffffffffu, v, off);
    __shared__ int ws[8];
    if ((t & 31) == 0) ws[t >> 5] = v;
    __syncthreads();
    if (t == 0) {
        int s = 0;
        #pragma unroll
        for (int w = 0; w < 8; w++) s += ws[w];
        g_bsum[blockIdx.x] = s;
    }
}

// ---------------- warp-shuffle scan (2 barriers) ----------------
__global__ __launch_bounds__(256) void k_scan_final() {
    int t = threadIdx.x;
    int lane = t & 31, warp = t >> 5;
    int i = blockIdx.x * 256 + t;

    // reduce bsum[0..bid)
    int b = (t < blockIdx.x) ? g_bsum[t] : 0;   // NBLK=196 < 256
    #pragma unroll
    for (int off = 16; off > 0; off >>= 1) b += __shfl_down_sync(0xffffffffu, b, off);
    __shared__ int ws[8], wt[8], s_blockoff;
    if (lane == 0) ws[warp] = b;

    // inclusive warp scan of cnt
    int v = (i < N_NODES) ? g_cnt[i] : 0;
    int incl = v;
    #pragma unroll
    for (int off = 1; off < 32; off <<= 1) {
        int n = __shfl_up_sync(0xffffffffu, incl, off);
        if (lane >= off) incl += n;
    }
    if (lane == 31) wt[warp] = incl;
    __syncthreads();
    if (t == 0) {
        int s = 0;
        #pragma unroll
        for (int w = 0; w < 8; w++) s += ws[w];
        s_blockoff = s;
    }
    __syncthreads();
    int warpbase = 0;
    #pragma unroll
    for (int w = 0; w < 8; w++) if (w < warp) warpbase += wt[w];

    if (i < N_NODES) {
        int rs = s_blockoff + warpbase + incl - v;   // exclusive
        g_rowstart[i] = rs;
        g_cursor[i]   = rs;
        g_dis[i]      = rsqrtf((float)(v + 1));
        g_cnt[i]      = 0;                 // self-clean for next replay
    }
    if (i == 0) g_rowstart[N_NODES] = N_EDGES;
}

// ---------------- fill: 2 edges/thread (independent atomic chains) ----------------
__global__ void k_fill(const int* __restrict__ ei) {
    int t = blockIdx.x * blockDim.x + threadIdx.x;
    if (t >= HALF_E) return;
    unsigned s0 = (unsigned)ei[t];
    unsigned d0 = (unsigned)ei[N_EDGES + t];
    unsigned s1 = (unsigned)ei[HALF_E + t];
    unsigned d1 = (unsigned)ei[N_EDGES + HALF_E + t];
    bool ok0 = (s0 < N_NODES) & (d0 < N_NODES);
    bool ok1 = (s1 < N_NODES) & (d1 < N_NODES);
    int p0 = ok0 ? atomicAdd(&g_cursor[d0], 1) : 0;
    int p1 = ok1 ? atomicAdd(&g_cursor[d1], 1) : 0;
    if (ok0) {
        float nm = g_dis[s0] * g_dis[d0];
        g_edge[p0] = ((unsigned long long)__float_as_uint(nm) << 32) | (unsigned long long)s0;
    }
    if (ok1) {
        float nm = g_dis[s1] * g_dis[d1];
        g_edge[p1] = ((unsigned long long)__float_as_uint(nm) << 32) | (unsigned long long)s1;
    }
}

// ---------------- gather-aggregate (warp per node, unroll 4) ----------------
__global__ __launch_bounds__(256) void k_gather(const float* __restrict__ x, int use_h,
                                                float* __restrict__ out2) {
    int idx = blockIdx.x * blockDim.x + threadIdx.x;
    int node = idx >> 5;
    if (node >= N_NODES) return;
    const float* in = use_h ? g_h : x;
    int lane = idx & 31;

    float di = g_dis[node];
    float c = di * di;
    float4 raw = ((const float4*)(in + (size_t)node * EMBED_DIM))[lane];
    if (out2) ((float4*)(out2 + (size_t)node * EMBED_DIM))[lane] = raw;
    float4 acc;
    acc.x = raw.x * c; acc.y = raw.y * c; acc.z = raw.z * c; acc.w = raw.w * c;

    int j   = g_rowstart[node];
    int end = g_rowstart[node + 1];

    for (; j + 4 <= end; j += 4) {
        unsigned long long p0 = g_edge[j],     p1 = g_edge[j + 1];
        unsigned long long p2 = g_edge[j + 2], p3 = g_edge[j + 3];
        int s0 = (int)(unsigned)p0, s1 = (int)(unsigned)p1;
        int s2 = (int)(unsigned)p2, s3 = (int)(unsigned)p3;
        float n0 = __uint_as_float((unsigned)(p0 >> 32));
        float n1 = __uint_as_float((unsigned)(p1 >> 32));
        float n2 = __uint_as_float((unsigned)(p2 >> 32));
        float n3 = __uint_as_float((unsigned)(p3 >> 32));
        float4 v0 = ((const float4*)(in + (size_t)s0 * EMBED_DIM))[lane];
        float4 v1 = ((const float4*)(in + (size_t)s1 * EMBED_DIM))[lane];
        float4 v2 = ((const float4*)(in + (size_t)s2 * EMBED_DIM))[lane];
        float4 v3 = ((const float4*)(in + (size_t)s3 * EMBED_DIM))[lane];
        acc.x += n0 * v0.x + n1 * v1.x + n2 * v2.x + n3 * v3.x;
        acc.y += n0 * v0.y + n1 * v1.y + n2 * v2.y + n3 * v3.y;
        acc.z += n0 * v0.z + n1 * v1.z + n2 * v2.z + n3 * v3.z;
        acc.w += n0 * v0.w + n1 * v1.w + n2 * v2.w + n3 * v3.w;
    }
    for (; j < end; j++) {
        unsigned long long p0 = g_edge[j];
        int s0 = (int)(unsigned)p0;
        float n0 = __uint_as_float((unsigned)(p0 >> 32));
        float4 v0 = ((const float4*)(in + (size_t)s0 * EMBED_DIM))[lane];
        acc.x += n0 * v0.x; acc.y += n0 * v0.y;
        acc.z += n0 * v0.z; acc.w += n0 * v0.w;
    }
    ((float4*)(g_agg + (size_t)node * EMBED_DIM))[lane] = acc;
}

// ---------------- HMMA bf16x3 GEMM + bias + tanh ----------------
#define PAD 136
#define A_IMG (64 * PAD * 2)
#define B_IMG (128 * PAD * 2)
#define SM_AH 0
#define SM_AL A_IMG
#define SM_BH (2 * A_IMG)
#define SM_BL (2 * A_IMG + B_IMG)
#define MMA_SMEM (2 * A_IMG + 2 * B_IMG)   // 104448 B

__device__ __forceinline__ uint32_t smem_u32(const void* p) {
    uint32_t a;
    asm("{ .reg .u64 t; cvta.to.shared.u64 t, %1; cvt.u32.u64 %0, t; }" : "=r"(a) : "l"(p));
    return a;
}
__device__ __forceinline__ void ldm_x4(uint32_t* r, uint32_t addr) {
    asm volatile("ldmatrix.sync.aligned.m8n8.x4.shared.b16 {%0,%1,%2,%3}, [%4];"
                 : "=r"(r[0]), "=r"(r[1]), "=r"(r[2]), "=r"(r[3]) : "r"(addr));
}
__device__ __forceinline__ void mma_bf16(float* d, const uint32_t* a, uint32_t b0, uint32_t b1) {
    asm volatile(
        "mma.sync.aligned.m16n8k16.row.col.f32.bf16.bf16.f32 "
        "{%0,%1,%2,%3}, {%4,%5,%6,%7}, {%8,%9}, {%0,%1,%2,%3};"
        : "+f"(d[0]), "+f"(d[1]), "+f"(d[2]), "+f"(d[3])
        : "r"(a[0]), "r"(a[1]), "r"(a[2]), "r"(a[3]), "r"(b0), "r"(b1));
}

__global__ __launch_bounds__(256) void k_mma_gemm(const float* __restrict__ bvec,
                                                  float* __restrict__ out,
                                                  int layer, int to_h) {
    extern __shared__ char sm[];
    __nv_bfloat16* sAH = (__nv_bfloat16*)(sm + SM_AH);
    __nv_bfloat16* sAL = (__nv_bfloat16*)(sm + SM_AL);
    int tid = threadIdx.x, wid = tid >> 5, lane = tid & 31;
    int row0 = blockIdx.x * 64;
    float* dst = to_h ? g_h : out;

    {
        const uint4* bh = (const uint4*)g_Bh[layer];
        const uint4* bl = (const uint4*)g_Bl[layer];
        #pragma unroll
        for (int i = 0; i < 8; i++) {
            int idx = tid + i * 256;
            int n = idx >> 4, c = idx & 15;
            *(uint4*)(sm + SM_BH + n * (PAD * 2) + c * 16) = bh[idx];
            *(uint4*)(sm + SM_BL + n * (PAD * 2) + c * 16) = bl[idx];
        }
    }
    #pragma unroll
    for (int i = 0; i < 32; i++) {
        int idx = tid + i * 256;
        int r = idx >> 7, k = idx & 127;
        int gr = row0 + r;
        float a = (gr < N_NODES) ? g_agg[(size_t)gr * EMBED_DIM + k] : 0.0f;
        __nv_bfloat16 ah = __float2bfloat16(a);
        __nv_bfloat16 al = __float2bfloat16(a - __bfloat162float(ah));
        sAH[r * PAD + k] = ah;
        sAL[r * PAD + k] = al;
    }
    __syncthreads();

    int m0 = (wid & 3) * 16;
    int n_base = (wid >> 2) * 64;

    uint32_t sb = smem_u32(sm);
    uint32_t aoff = (uint32_t)((m0 + (lane & 15)) * (PAD * 2) + (lane & 16));
    uint32_t aAddrH = sb + SM_AH + aoff;
    uint32_t aAddrL = sb + SM_AL + aoff;
    uint32_t bAddrH[4], bAddrL[4];
    #pragma unroll
    for (int p = 0; p < 4; p++) {
        int n = n_base + p * 16 + (lane & 7) + ((lane >> 1) & 8);
        uint32_t boff = (uint32_t)(n * (PAD * 2) + (lane & 8) * 2);
        bAddrH[p] = sb + SM_BH + boff;
        bAddrL[p] = sb + SM_BL + boff;
    }

    float d[8][4];
    #pragma unroll
    for (int t = 0; t < 8; t++)
        #pragma unroll
        for (int q = 0; q < 4; q++) d[t][q] = 0.0f;

    #pragma unroll
    for (int kk = 0; kk < 8; kk++) {
        uint32_t kb = kk * 32;
        uint32_t ah[4], al[4], bh[4][4], bl[4][4];
        ldm_x4(ah, aAddrH + kb);
        ldm_x4(al, aAddrL + kb);
        #pragma unroll
        for (int p = 0; p < 4; p++) {
            ldm_x4(bh[p], bAddrH[p] + kb);
            ldm_x4(bl[p], bAddrL[p] + kb);
        }
        #pragma unroll
        for (int p = 0; p < 4; p++) {
            #pragma unroll
            for (int q = 0; q < 2; q++) {
                int t = p * 2 + q;
                mma_bf16(d[t], ah, bh[p][2 * q], bh[p][2 * q + 1]);
                mma_bf16(d[t], ah, bl[p][2 * q], bl[p][2 * q + 1]);
                mma_bf16(d[t], al, bh[p][2 * q], bh[p][2 * q + 1]);
            }
        }
    }

    int g = lane >> 2;
    int c2 = (lane & 3) * 2;
    int rowA = row0 + m0 + g;
    int rowB = rowA + 8;
    #pragma unroll
    for (int t = 0; t < 8; t++) {
        int col = n_base + t * 8 + c2;
        float bx = bvec[col], by = bvec[col + 1];
        if (rowA < N_NODES) {
            float2 o;
            o.x = tanhf(d[t][0] + bx);
            o.y = tanhf(d[t][1] + by);
            *(float2*)(dst + (size_t)rowA * EMBED_DIM + col) = o;
        }
        if (rowB < N_NODES) {
            float2 o;
            o.x = tanhf(d[t][2] + bx);
            o.y = tanhf(d[t][3] + by);
            *(float2*)(dst + (size_t)rowB * EMBED_DIM + col) = o;
        }
    }
}

extern "C" void kernel_launch(void* const* d_in, const int* in_sizes, int n_in,
                              void* d_out, int out_size) {
    const float* x  = (const float*)d_in[0];
    const int*   ei = (const int*)d_in[1];
    const float* W1 = (const float*)d_in[2];
    const float* b1 = (const float*)d_in[3];
    const float* W2 = (const float*)d_in[4];
    const float* b2 = (const float*)d_in[5];
    float* out = (float*)d_out;

    cudaFuncSetAttribute(k_mma_gemm,
                         cudaFuncAttributeMaxDynamicSharedMemorySize, MMA_SMEM);

    const int NT = 256;
    int blksE2 = (HALF_E + NT - 1) / NT;          // 977
    int blksND = (N_NODES * 32 + NT - 1) / NT;    // 6250
    int blksG  = (N_NODES + 63) / 64;             // 782

    // CSR build (g_cnt zero at entry; self-cleaned in scan)
    k_hist<<<blksE2, NT>>>(ei, W1, W2);
    k_blocksum<<<NBLK, NT>>>();
    k_scan_final<<<NBLK, NT>>>();
    k_fill<<<blksE2, NT>>>(ei);

    float* out2 = (out_size >= 2 * N_NODES * EMBED_DIM)
                ? out + (size_t)N_NODES * EMBED_DIM : nullptr;

    // layer 1 (gather also writes the identity copy of x)
    k_gather<<<blksND, NT>>>(x, 0, out2);
    k_mma_gemm<<<blksG, NT, MMA_SMEM>>>(b1, out, 0, 1);

    // layer 2
    k_gather<<<blksND, NT>>>(x, 1, nullptr);
    k_mma_gemm<<<blksG, NT, MMA_SMEM>>>(b2, out, 1, 0);
}

// round 13
// speedup vs baseline: 1.3190x; 1.0184x over previous
#include <cuda_runtime.h>
#include <cuda_bf16.h>
#include <cstdint>

#define N_NODES 50000
#define EMBED_DIM 128
#define N_EDGES 500000
#define NBLK ((N_NODES + 255) / 256)   // 196

// ---------------- device scratch (zero-initialized at module load) ----------------
__device__ int   g_cnt[N_NODES];          // self-cleaning histogram
__device__ int   g_bsum[NBLK];
__device__ int   g_rowstart[N_NODES + 1];
__device__ int   g_cursor[N_NODES];
__device__ unsigned long long g_edge[N_EDGES];   // packed {val_f32<<32 | col}
__device__ float g_dis[N_NODES];
__device__ float g_agg[N_NODES * EMBED_DIM];
__device__ float g_h[N_NODES * EMBED_DIM];
// W split images, transposed: Bh[layer][n*128+k] = bf16_hi(W[k][n])
__device__ __nv_bfloat16 g_Bh[2][128 * 128];
__device__ __nv_bfloat16 g_Bl[2][128 * 128];

// ---------------- hist (1 edge/thread, fused weight prep) — R9 proven ----------------
__global__ void k_hist(const int* __restrict__ ei,
                       const float* __restrict__ W1, const float* __restrict__ W2) {
    int e = blockIdx.x * blockDim.x + threadIdx.x;
    if (e < N_EDGES) {
        unsigned d = (unsigned)ei[N_EDGES + e];
        if (d < N_NODES) atomicAdd(&g_cnt[d], 1);
    }
    if (blockIdx.x < 128) {
        int idx = blockIdx.x * blockDim.x + threadIdx.x;
        int layer = idx >> 14;
        int t = idx & 16383;
        int k = t >> 7, n = t & 127;
        const float* W = layer ? W2 : W1;
        float w = W[k * 128 + n];
        __nv_bfloat16 wh = __float2bfloat16(w);
        __nv_bfloat16 wl = __float2bfloat16(w - __bfloat162float(wh));
        g_Bh[layer][n * 128 + k] = wh;
        g_Bl[layer][n * 128 + k] = wl;
    }
}

// ---------------- warp-shuffle block sum ----------------
__global__ __launch_bounds__(256) void k_blocksum() {
    int t = threadIdx.x;
    int i = blockIdx.x * 256 + t;
    int v = (i < N_NODES) ? g_cnt[i] : 0;
    #pragma unroll
    for (int off = 16; off > 0; off >>= 1) v += __shfl_down_sync(0xffffffffu, v, off);
    __shared__ int ws[8];
    if ((t & 31) == 0) ws[t >> 5] = v;
    __syncthreads();
    if (t == 0) {
        int s = 0;
        #pragma unroll
        for (int w = 0; w < 8; w++) s += ws[w];
        g_bsum[blockIdx.x] = s;
    }
}

// ---------------- warp-shuffle scan (2 barriers) ----------------
__global__ __launch_bounds__(256) void k_scan_final() {
    int t = threadIdx.x;
    int lane = t & 31, warp = t >> 5;
    int i = blockIdx.x * 256 + t;

    // reduce bsum[0..bid)
    int b = (t < blockIdx.x) ? g_bsum[t] : 0;   // NBLK=196 < 256
    #pragma unroll
    for (int off = 16; off > 0; off >>= 1) b += __shfl_down_sync(0xffffffffu, b, off);
    __shared__ int ws[8], wt[8], s_blockoff;
    if (lane == 0) ws[warp] = b;

    // inclusive warp scan of cnt
    int v = (i < N_NODES) ? g_cnt[i] : 0;
    int incl = v;
    #pragma unroll
    for (int off = 1; off < 32; off <<= 1) {
        int n = __shfl_up_sync(0xffffffffu, incl, off);
        if (lane >= off) incl += n;
    }
    if (lane == 31) wt[warp] = incl;
    __syncthreads();
    if (t == 0) {
        int s = 0;
        #pragma unroll
        for (int w = 0; w < 8; w++) s += ws[w];
        s_blockoff = s;
    }
    __syncthreads();
    int warpbase = 0;
    #pragma unroll
    for (int w = 0; w < 8; w++) if (w < warp) warpbase += wt[w];

    if (i < N_NODES) {
        int rs = s_blockoff + warpbase + incl - v;   // exclusive
        g_rowstart[i] = rs;
        g_cursor[i]   = rs;
        g_dis[i]      = rsqrtf((float)(v + 1));
        g_cnt[i]      = 0;                 // self-clean for next replay
    }
    if (i == 0) g_rowstart[N_NODES] = N_EDGES;
}

// ---------------- fill (1 edge/thread) — R9 proven ----------------
__global__ void k_fill(const int* __restrict__ ei) {
    int e = blockIdx.x * blockDim.x + threadIdx.x;
    if (e >= N_EDGES) return;
    unsigned s = (unsigned)ei[e];
    unsigned d = (unsigned)ei[N_EDGES + e];
    if (s >= N_NODES || d >= N_NODES) return;
    int pos = atomicAdd(&g_cursor[d], 1);
    float nm = g_dis[s] * g_dis[d];
    g_edge[pos] = ((unsigned long long)__float_as_uint(nm) << 32) | (unsigned long long)s;
}

// ---------------- gather-aggregate (warp per node, unroll 4) — R9 proven ----------------
__global__ __launch_bounds__(256) void k_gather(const float* __restrict__ x, int use_h,
                                                float* __restrict__ out2) {
    int idx = blockIdx.x * blockDim.x + threadIdx.x;
    int node = idx >> 5;
    if (node >= N_NODES) return;
    const float* in = use_h ? g_h : x;
    int lane = idx & 31;

    float di = g_dis[node];
    float c = di * di;
    float4 raw = ((const float4*)(in + (size_t)node * EMBED_DIM))[lane];
    if (out2) ((float4*)(out2 + (size_t)node * EMBED_DIM))[lane] = raw;
    float4 acc;
    acc.x = raw.x * c; acc.y = raw.y * c; acc.z = raw.z * c; acc.w = raw.w * c;

    int j   = g_rowstart[node];
    int end = g_rowstart[node + 1];

    for (; j + 4 <= end; j += 4) {
        unsigned long long p0 = g_edge[j],     p1 = g_edge[j + 1];
        unsigned long long p2 = g_edge[j + 2], p3 = g_edge[j + 3];
        int s0 = (int)(unsigned)p0, s1 = (int)(unsigned)p1;
        int s2 = (int)(unsigned)p2, s3 = (int)(unsigned)p3;
        float n0 = __uint_as_float((unsigned)(p0 >> 32));
        float n1 = __uint_as_float((unsigned)(p1 >> 32));
        float n2 = __uint_as_float((unsigned)(p2 >> 32));
        float n3 = __uint_as_float((unsigned)(p3 >> 32));
        float4 v0 = ((const float4*)(in + (size_t)s0 * EMBED_DIM))[lane];
        float4 v1 = ((const float4*)(in + (size_t)s1 * EMBED_DIM))[lane];
        float4 v2 = ((const float4*)(in + (size_t)s2 * EMBED_DIM))[lane];
        float4 v3 = ((const float4*)(in + (size_t)s3 * EMBED_DIM))[lane];
        acc.x += n0 * v0.x + n1 * v1.x + n2 * v2.x + n3 * v3.x;
        acc.y += n0 * v0.y + n1 * v1.y + n2 * v2.y + n3 * v3.y;
        acc.z += n0 * v0.z + n1 * v1.z + n2 * v2.z + n3 * v3.z;
        acc.w += n0 * v0.w + n1 * v1.w + n2 * v2.w + n3 * v3.w;
    }
    for (; j < end; j++) {
        unsigned long long p0 = g_edge[j];
        int s0 = (int)(unsigned)p0;
        float n0 = __uint_as_float((unsigned)(p0 >> 32));
        float4 v0 = ((const float4*)(in + (size_t)s0 * EMBED_DIM))[lane];
        acc.x += n0 * v0.x; acc.y += n0 * v0.y;
        acc.z += n0 * v0.z; acc.w += n0 * v0.w;
    }
    ((float4*)(g_agg + (size_t)node * EMBED_DIM))[lane] = acc;
}

// ---------------- HMMA bf16x3 GEMM + bias + tanh — R8 proven ----------------
#define PAD 136
#define A_IMG (64 * PAD * 2)
#define B_IMG (128 * PAD * 2)
#define SM_AH 0
#define SM_AL A_IMG
#define SM_BH (2 * A_IMG)
#define SM_BL (2 * A_IMG + B_IMG)
#define MMA_SMEM (2 * A_IMG + 2 * B_IMG)   // 104448 B

__device__ __forceinline__ uint32_t smem_u32(const void* p) {
    uint32_t a;
    asm("{ .reg .u64 t; cvta.to.shared.u64 t, %1; cvt.u32.u64 %0, t; }" : "=r"(a) : "l"(p));
    return a;
}
__device__ __forceinline__ void ldm_x4(uint32_t* r, uint32_t addr) {
    asm volatile("ldmatrix.sync.aligned.m8n8.x4.shared.b16 {%0,%1,%2,%3}, [%4];"
                 : "=r"(r[0]), "=r"(r[1]), "=r"(r[2]), "=r"(r[3]) : "r"(addr));
}
__device__ __forceinline__ void mma_bf16(float* d, const uint32_t* a, uint32_t b0, uint32_t b1) {
    asm volatile(
        "mma.sync.aligned.m16n8k16.row.col.f32.bf16.bf16.f32 "
        "{%0,%1,%2,%3}, {%4,%5,%6,%7}, {%8,%9}, {%0,%1,%2,%3};"
        : "+f"(d[0]), "+f"(d[1]), "+f"(d[2]), "+f"(d[3])
        : "r"(a[0]), "r"(a[1]), "r"(a[2]), "r"(a[3]), "r"(b0), "r"(b1));
}

__global__ __launch_bounds__(256) void k_mma_gemm(const float* __restrict__ bvec,
                                                  float* __restrict__ out,
                                                  int layer, int to_h) {
    extern __shared__ char sm[];
    __nv_bfloat16* sAH = (__nv_bfloat16*)(sm + SM_AH);
    __nv_bfloat16* sAL = (__nv_bfloat16*)(sm + SM_AL);
    int tid = threadIdx.x, wid = tid >> 5, lane = tid & 31;
    int row0 = blockIdx.x * 64;
    float* dst = to_h ? g_h : out;

    {
        const uint4* bh = (const uint4*)g_Bh[layer];
        const uint4* bl = (const uint4*)g_Bl[layer];
        #pragma unroll
        for (int i = 0; i < 8; i++) {
            int idx = tid + i * 256;
            int n = idx >> 4, c = idx & 15;
            *(uint4*)(sm + SM_BH + n * (PAD * 2) + c * 16) = bh[idx];
            *(uint4*)(sm + SM_BL + n * (PAD * 2) + c * 16) = bl[idx];
        }
    }
    #pragma unroll
    for (int i = 0; i < 32; i++) {
        int idx = tid + i * 256;
        int r = idx >> 7, k = idx & 127;
        int gr = row0 + r;
        float a = (gr < N_NODES) ? g_agg[(size_t)gr * EMBED_DIM + k] : 0.0f;
        __nv_bfloat16 ah = __float2bfloat16(a);
        __nv_bfloat16 al = __float2bfloat16(a - __bfloat162float(ah));
        sAH[r * PAD + k] = ah;
        sAL[r * PAD + k] = al;
    }
    __syncthreads();

    int m0 = (wid & 3) * 16;
    int n_base = (wid >> 2) * 64;

    uint32_t sb = smem_u32(sm);
    uint32_t aoff = (uint32_t)((m0 + (lane & 15)) * (PAD * 2) + (lane & 16));
    uint32_t aAddrH = sb + SM_AH + aoff;
    uint32_t aAddrL = sb + SM_AL + aoff;
    uint32_t bAddrH[4], bAddrL[4];
    #pragma unroll
    for (int p = 0; p < 4; p++) {
        int n = n_base + p * 16 + (lane & 7) + ((lane >> 1) & 8);
        uint32_t boff = (uint32_t)(n * (PAD * 2) + (lane & 8) * 2);
        bAddrH[p] = sb + SM_BH + boff;
        bAddrL[p] = sb + SM_BL + boff;
    }

    float d[8][4];
    #pragma unroll
    for (int t = 0; t < 8; t++)
        #pragma unroll
        for (int q = 0; q < 4; q++) d[t][q] = 0.0f;

    #pragma unroll
    for (int kk = 0; kk < 8; kk++) {
        uint32_t kb = kk * 32;
        uint32_t ah[4], al[4], bh[4][4], bl[4][4];
        ldm_x4(ah, aAddrH + kb);
        ldm_x4(al, aAddrL + kb);
        #pragma unroll
        for (int p = 0; p < 4; p++) {
            ldm_x4(bh[p], bAddrH[p] + kb);
            ldm_x4(bl[p], bAddrL[p] + kb);
        }
        #pragma unroll
        for (int p = 0; p < 4; p++) {
            #pragma unroll
            for (int q = 0; q < 2; q++) {
                int t = p * 2 + q;
                mma_bf16(d[t], ah, bh[p][2 * q], bh[p][2 * q + 1]);
                mma_bf16(d[t], ah, bl[p][2 * q], bl[p][2 * q + 1]);
                mma_bf16(d[t], al, bh[p][2 * q], bh[p][2 * q + 1]);
            }
        }
    }

    int g = lane >> 2;
    int c2 = (lane & 3) * 2;
    int rowA = row0 + m0 + g;
    int rowB = rowA + 8;
    #pragma unroll
    for (int t = 0; t < 8; t++) {
        int col = n_base + t * 8 + c2;
        float bx = bvec[col], by = bvec[col + 1];
        if (rowA < N_NODES) {
            float2 o;
            o.x = tanhf(d[t][0] + bx);
            o.y = tanhf(d[t][1] + by);
            *(float2*)(dst + (size_t)rowA * EMBED_DIM + col) = o;
        }
        if (rowB < N_NODES) {
            float2 o;
            o.x = tanhf(d[t][2] + bx);
            o.y = tanhf(d[t][3] + by);
            *(float2*)(dst + (size_t)rowB * EMBED_DIM + col) = o;
        }
    }
}

extern "C" void kernel_launch(void* const* d_in, const int* in_sizes, int n_in,
                              void* d_out, int out_size) {
    const float* x  = (const float*)d_in[0];
    const int*   ei = (const int*)d_in[1];
    const float* W1 = (const float*)d_in[2];
    const float* b1 = (const float*)d_in[3];
    const float* W2 = (const float*)d_in[4];
    const float* b2 = (const float*)d_in[5];
    float* out = (float*)d_out;

    cudaFuncSetAttribute(k_mma_gemm,
                         cudaFuncAttributeMaxDynamicSharedMemorySize, MMA_SMEM);

    const int NT = 256;
    int blksE  = (N_EDGES + NT - 1) / NT;        // 1954
    int blksND = (N_NODES * 32 + NT - 1) / NT;   // 6250
    int blksG  = (N_NODES + 63) / 64;            // 782

    // CSR build (g_cnt zero at entry; self-cleaned in scan)
    k_hist<<<blksE, NT>>>(ei, W1, W2);
    k_blocksum<<<NBLK, NT>>>();
    k_scan_final<<<NBLK, NT>>>();
    k_fill<<<blksE, NT>>>(ei);

    float* out2 = (out_size >= 2 * N_NODES * EMBED_DIM)
                ? out + (size_t)N_NODES * EMBED_DIM : nullptr;

    // layer 1 (gather also writes the identity copy of x)
    k_gather<<<blksND, NT>>>(x, 0, out2);
    k_mma_gemm<<<blksG, NT, MMA_SMEM>>>(b1, out, 0, 1);

    // layer 2
    k_gather<<<blksND, NT>>>(x, 1, nullptr);
    k_mma_gemm<<<blksG, NT, MMA_SMEM>>>(b2, out, 1, 0);
}